// round 3
// baseline (speedup 1.0000x reference)
#include <cuda_runtime.h>
#include <math.h>

#define B_  2
#define L_  2048
#define D_  1024
#define H_  16
#define DH_ 64
#define M_  (B_*L_)   // 4096 rows

// Scratch (allocation-free rule): Q, K, V, attention output. 16 MB each.
__device__ float g_Q [(size_t)M_*D_];
__device__ float g_K [(size_t)M_*D_];
__device__ float g_V [(size_t)M_*D_];
__device__ float g_Ao[(size_t)M_*D_];

// ---------------------------------------------------------------------------
// C[M,N] = A[M,K] @ W[N,K]^T   (both K-contiguous row-major: "NT" gemm)
// 64x64 tile, BK=16, 256 threads, 4x4 register tile per thread.
// ---------------------------------------------------------------------------
__global__ void __launch_bounds__(256)
gemm_nt64(const float* __restrict__ A, const float* __restrict__ W,
          float* __restrict__ C, int M, int N, int K)
{
    __shared__ float As[16][65];
    __shared__ float Ws[16][65];
    const int tx = threadIdx.x, ty = threadIdx.y;
    const int t  = ty * 16 + tx;
    const int m0 = blockIdx.y * 64, n0 = blockIdx.x * 64;
    const int ml = t >> 2;           // 0..63 local row for loading
    const int q4 = (t & 3) * 4;      // k-quad * 4

    float acc[4][4] = {};

    for (int k0 = 0; k0 < K; k0 += 16) {
        float4 av = *(const float4*)(A + (size_t)(m0 + ml) * K + k0 + q4);
        float4 wv = *(const float4*)(W + (size_t)(n0 + ml) * K + k0 + q4);
        As[q4+0][ml] = av.x; As[q4+1][ml] = av.y;
        As[q4+2][ml] = av.z; As[q4+3][ml] = av.w;
        Ws[q4+0][ml] = wv.x; Ws[q4+1][ml] = wv.y;
        Ws[q4+2][ml] = wv.z; Ws[q4+3][ml] = wv.w;
        __syncthreads();
        #pragma unroll
        for (int kk = 0; kk < 16; kk++) {
            float a[4], b[4];
            #pragma unroll
            for (int i = 0; i < 4; i++) a[i] = As[kk][i*16 + ty];
            #pragma unroll
            for (int j = 0; j < 4; j++) b[j] = Ws[kk][j*16 + tx];
            #pragma unroll
            for (int i = 0; i < 4; i++)
                #pragma unroll
                for (int j = 0; j < 4; j++)
                    acc[i][j] = fmaf(a[i], b[j], acc[i][j]);
        }
        __syncthreads();
    }
    #pragma unroll
    for (int i = 0; i < 4; i++)
        #pragma unroll
        for (int j = 0; j < 4; j++)
            C[(size_t)(m0 + i*16 + ty) * N + n0 + j*16 + tx] = acc[i][j];
}

// ---------------------------------------------------------------------------
// Causal flash attention, per (b, h): 64-query tile per block,
// iterate kv tiles 0..qb, online softmax, 4x4 register tiles, 256 threads.
// Q rows owned per thread: ty*4+i ; S cols / O dims owned: tx*4+j.
// ---------------------------------------------------------------------------
#define PADR 65

__global__ void __launch_bounds__(256)
attn_kernel()
{
    extern __shared__ float sm[];
    float* sQ  = sm;                 // [64][PADR]
    float* sKV = sm + 64 * PADR;     // [64][PADR], K then V
    float* sP  = sm + 2 * 64 * PADR; // [64][PADR]

    const int tx  = threadIdx.x, ty = threadIdx.y;
    const int tid = ty * 16 + tx;
    const int qb  = blockIdx.x;             // 0..31
    const int b   = blockIdx.y >> 4;
    const int h   = blockIdx.y & 15;

    const size_t base = (size_t)b * L_ * D_ + (size_t)h * DH_;
    const float* Qp = g_Q + base;
    const float* Kp = g_K + base;
    const float* Vp = g_V + base;

    // Load the 64x64 Q tile
    for (int idx = tid; idx < 64 * 64; idx += 256) {
        int r = idx >> 6, c = idx & 63;
        sQ[r * PADR + c] = Qp[(size_t)(qb * 64 + r) * D_ + c];
    }

    float Mx[4], Ls[4], O[4][4];
    #pragma unroll
    for (int i = 0; i < 4; i++) {
        Mx[i] = -INFINITY; Ls[i] = 0.f;
        #pragma unroll
        for (int j = 0; j < 4; j++) O[i][j] = 0.f;
    }

    for (int kb = 0; kb <= qb; kb++) {
        __syncthreads();  // prev iter done with sKV/sP (also covers Q load)
        // Load K tile
        for (int idx = tid; idx < 64 * 64; idx += 256) {
            int r = idx >> 6, c = idx & 63;
            sKV[r * PADR + c] = Kp[(size_t)(kb * 64 + r) * D_ + c];
        }
        __syncthreads();

        // S = Q K^T / sqrt(DH)
        float S[4][4] = {};
        #pragma unroll 8
        for (int d = 0; d < 64; d++) {
            float a[4], kv[4];
            #pragma unroll
            for (int i = 0; i < 4; i++) a[i]  = sQ [(ty*4 + i) * PADR + d];
            #pragma unroll
            for (int j = 0; j < 4; j++) kv[j] = sKV[(tx*4 + j) * PADR + d];
            #pragma unroll
            for (int i = 0; i < 4; i++)
                #pragma unroll
                for (int j = 0; j < 4; j++)
                    S[i][j] = fmaf(a[i], kv[j], S[i][j]);
        }
        const bool diag = (kb == qb);
        #pragma unroll
        for (int i = 0; i < 4; i++) {
            #pragma unroll
            for (int j = 0; j < 4; j++) {
                float sv = S[i][j] * 0.125f;     // 1/sqrt(64)
                if (diag && (tx*4 + j) > (ty*4 + i)) sv = -INFINITY;
                S[i][j] = sv;
            }
        }

        // Online softmax per owned row, reduction across the 16 tx lanes
        #pragma unroll
        for (int i = 0; i < 4; i++) {
            float mx = fmaxf(fmaxf(S[i][0], S[i][1]), fmaxf(S[i][2], S[i][3]));
            #pragma unroll
            for (int o = 8; o > 0; o >>= 1)
                mx = fmaxf(mx, __shfl_xor_sync(0xffffffffu, mx, o));
            float newM = fmaxf(Mx[i], mx);
            float corr = __expf(Mx[i] - newM);   // first tile: exp(-inf)=0
            Mx[i] = newM;
            Ls[i] *= corr;
            #pragma unroll
            for (int j = 0; j < 4; j++) O[i][j] *= corr;

            float P[4], rs = 0.f;
            #pragma unroll
            for (int j = 0; j < 4; j++) {
                P[j] = __expf(S[i][j] - newM);   // masked -> 0
                rs += P[j];
            }
            #pragma unroll
            for (int o = 8; o > 0; o >>= 1)
                rs += __shfl_xor_sync(0xffffffffu, rs, o);
            Ls[i] += rs;
            #pragma unroll
            for (int j = 0; j < 4; j++)
                sP[(ty*4 + i) * PADR + tx*4 + j] = P[j];
        }
        __syncthreads();  // sP written, sKV(K) reads done

        // Load V tile (overwrites K)
        for (int idx = tid; idx < 64 * 64; idx += 256) {
            int r = idx >> 6, c = idx & 63;
            sKV[r * PADR + c] = Vp[(size_t)(kb * 64 + r) * D_ + c];
        }
        __syncthreads();

        // O += P @ V
        #pragma unroll 8
        for (int k = 0; k < 64; k++) {
            float p[4], v[4];
            #pragma unroll
            for (int i = 0; i < 4; i++) p[i] = sP [(ty*4 + i) * PADR + k];
            #pragma unroll
            for (int j = 0; j < 4; j++) v[j] = sKV[k * PADR + tx*4 + j];
            #pragma unroll
            for (int i = 0; i < 4; i++)
                #pragma unroll
                for (int j = 0; j < 4; j++)
                    O[i][j] = fmaf(p[i], v[j], O[i][j]);
        }
    }

    // Epilogue: normalize + write (float4, coalesced)
    float* Op = g_Ao + base;
    #pragma unroll
    for (int i = 0; i < 4; i++) {
        float inv = 1.f / Ls[i];
        float4 o4 = make_float4(O[i][0]*inv, O[i][1]*inv, O[i][2]*inv, O[i][3]*inv);
        *(float4*)(Op + (size_t)(qb*64 + ty*4 + i) * D_ + tx*4) = o4;
    }
}

// ---------------------------------------------------------------------------
extern "C" void kernel_launch(void* const* d_in, const int* in_sizes, int n_in,
                              void* d_out, int out_size)
{
    const float* x  = (const float*)d_in[0];
    // d_in[1] = mask (int32 tril) — causality is applied analytically
    const float* Wq = (const float*)d_in[2];
    const float* Wk = (const float*)d_in[3];
    const float* Wv = (const float*)d_in[4];
    const float* Wo = (const float*)d_in[5];
    float* out = (float*)d_out;

    void *pQ, *pK, *pV, *pA;
    cudaGetSymbolAddress(&pQ, g_Q);
    cudaGetSymbolAddress(&pK, g_K);
    cudaGetSymbolAddress(&pV, g_V);
    cudaGetSymbolAddress(&pA, g_Ao);

    dim3 blk(16, 16);
    dim3 grd(D_ / 64, M_ / 64);

    gemm_nt64<<<grd, blk>>>(x, Wq, (float*)pQ, M_, D_, D_);
    gemm_nt64<<<grd, blk>>>(x, Wk, (float*)pK, M_, D_, D_);
    gemm_nt64<<<grd, blk>>>(x, Wv, (float*)pV, M_, D_, D_);

    const int smem = 3 * 64 * PADR * (int)sizeof(float);  // 49920 B
    cudaFuncSetAttribute(attn_kernel,
                         cudaFuncAttributeMaxDynamicSharedMemorySize, smem);
    attn_kernel<<<dim3(L_ / 64, B_ * H_), blk, smem>>>();

    gemm_nt64<<<grd, blk>>>((const float*)pA, Wo, out, M_, D_, D_);
}